// round 6
// baseline (speedup 1.0000x reference)
#include <cuda_runtime.h>
#include <cstdint>

// Problem constants
#define BATCH 4
#define DIM   512
#define HEADS 8
#define DHEAD 64
#define HW    4096   // 64*64 query positions
#define LKV   1024   // 32*32 kv positions

// Scratch (device globals; allocation-free per harness rules)
__device__ float g_q [BATCH * DIM * HW];        // Q  [b][hd][s]
__device__ float g_kv[BATCH * 2 * DIM * LKV];   // KV [b][o][ij]
__device__ float g_o [BATCH * DIM * HW];        // attn out

// ---------------------------------------------------------------------------
// tf32 helpers
// ---------------------------------------------------------------------------
__device__ __forceinline__ uint32_t f2t(float f) {
    uint32_t u;
    asm("cvt.rna.tf32.f32 %0, %1;" : "=r"(u) : "f"(f));
    return u;
}

__device__ __forceinline__ void mma8(float& d0, float& d1, float& d2, float& d3,
                                     uint32_t a0, uint32_t a1, uint32_t a2, uint32_t a3,
                                     uint32_t b0, uint32_t b1) {
    asm("mma.sync.aligned.m16n8k8.row.col.f32.tf32.tf32.f32 "
        "{%0,%1,%2,%3},{%4,%5,%6,%7},{%8,%9},{%0,%1,%2,%3};"
        : "+f"(d0), "+f"(d1), "+f"(d2), "+f"(d3)
        : "r"(a0), "r"(a1), "r"(a2), "r"(a3), "r"(b0), "r"(b1));
}

// ---------------------------------------------------------------------------
// tf32 tensor-core GEMM, 256 threads (8 warps), warp tile 32x64.
// C[b] = A @ B[b]; A [M,K] row-major shared; B [K,N] batched; C [M,N].
// CTA 128x128, BK=16, double-buffered smem + register prefetch.
// ---------------------------------------------------------------------------
#define GLD 136

template <int M, int N, int K>
__global__ __launch_bounds__(256, 2)
void gemm_tf32(const float* __restrict__ A,
               const float* __restrict__ Bsrc,
               float* __restrict__ Csrc)
{
    __shared__ uint32_t As[2][16 * GLD];
    __shared__ uint32_t Bs[2][16 * GLD];

    const int tid  = threadIdx.x;
    const int lane = tid & 31;
    const int w    = tid >> 5;          // 0..7
    const int g    = lane >> 2;
    const int t    = lane & 3;
    const int m0w  = (w >> 1) * 32;     // 4 warp-rows of 32
    const int n0w  = (w & 1) * 64;      // 2 warp-cols of 64
    const int row0 = blockIdx.y * 128;
    const int col0 = blockIdx.x * 128;

    const float* Bp = Bsrc + (size_t)blockIdx.z * K * N;
    float*       Cp = Csrc + (size_t)blockIdx.z * M * N;

    const int ar = tid >> 1;            // 0..127
    const int ac = (tid & 1) * 8;       // 0 or 8
    const int br = tid >> 5;            // 0..7 (+8)
    const int bc = (tid & 31) * 4;

    float a_regs[8];
    float4 b_regs[2];

    auto LDG = [&](int k0) {
        const float* ap = A + (size_t)(row0 + ar) * K + k0 + ac;
        *reinterpret_cast<float4*>(&a_regs[0]) = *reinterpret_cast<const float4*>(ap);
        *reinterpret_cast<float4*>(&a_regs[4]) = *reinterpret_cast<const float4*>(ap + 4);
#pragma unroll
        for (int it = 0; it < 2; it++)
            b_regs[it] = *reinterpret_cast<const float4*>(
                Bp + (size_t)(k0 + br + it * 8) * N + col0 + bc);
    };
    auto STS = [&](int buf) {
#pragma unroll
        for (int j = 0; j < 8; j++)
            As[buf][(ac + j) * GLD + ar] = f2t(a_regs[j]);
#pragma unroll
        for (int it = 0; it < 2; it++) {
            uint4 u;
            u.x = f2t(b_regs[it].x); u.y = f2t(b_regs[it].y);
            u.z = f2t(b_regs[it].z); u.w = f2t(b_regs[it].w);
            *reinterpret_cast<uint4*>(&Bs[buf][(br + it * 8) * GLD + bc]) = u;
        }
    };

    float acc[2][8][4];
#pragma unroll
    for (int mt = 0; mt < 2; mt++)
#pragma unroll
        for (int nt = 0; nt < 8; nt++)
#pragma unroll
            for (int r = 0; r < 4; r++) acc[mt][nt][r] = 0.f;

    LDG(0);
    STS(0);
    __syncthreads();

    constexpr int NIT = K / 16;
    for (int i = 0; i < NIT; i++) {
        const int buf = i & 1;
        if (i + 1 < NIT) LDG((i + 1) * 16);

#pragma unroll
        for (int s = 0; s < 2; s++) {
            uint32_t a[2][4], b[8][2];
#pragma unroll
            for (int mt = 0; mt < 2; mt++) {
                const uint32_t* p0 = &As[buf][(s * 8 + t) * GLD + m0w + mt * 16 + g];
                const uint32_t* p1 = &As[buf][(s * 8 + t + 4) * GLD + m0w + mt * 16 + g];
                a[mt][0] = p0[0]; a[mt][1] = p0[8];
                a[mt][2] = p1[0]; a[mt][3] = p1[8];
            }
#pragma unroll
            for (int nt = 0; nt < 8; nt++) {
                b[nt][0] = Bs[buf][(s * 8 + t) * GLD + n0w + nt * 8 + g];
                b[nt][1] = Bs[buf][(s * 8 + t + 4) * GLD + n0w + nt * 8 + g];
            }
#pragma unroll
            for (int mt = 0; mt < 2; mt++)
#pragma unroll
                for (int nt = 0; nt < 8; nt++)
                    mma8(acc[mt][nt][0], acc[mt][nt][1], acc[mt][nt][2], acc[mt][nt][3],
                         a[mt][0], a[mt][1], a[mt][2], a[mt][3],
                         b[nt][0], b[nt][1]);
        }
        if (i + 1 < NIT) STS(buf ^ 1);
        __syncthreads();
    }

#pragma unroll
    for (int mt = 0; mt < 2; mt++)
#pragma unroll
        for (int nt = 0; nt < 8; nt++) {
            float* c0 = Cp + (size_t)(row0 + m0w + mt * 16 + g) * N
                           + col0 + n0w + nt * 8 + 2 * t;
            float2 v0; v0.x = acc[mt][nt][0]; v0.y = acc[mt][nt][1];
            float2 v1; v1.x = acc[mt][nt][2]; v1.y = acc[mt][nt][3];
            *reinterpret_cast<float2*>(c0)                 = v0;
            *reinterpret_cast<float2*>(c0 + 8 * (size_t)N) = v1;
        }
}

// ---------------------------------------------------------------------------
// KV conv as implicit-im2col tf32 GEMM, same 256-thread tiling.
// M=1024, N=1024, K=2048. k = c*4 + p*2 + q; n = i*32 + j.
// ---------------------------------------------------------------------------
__global__ __launch_bounds__(256, 2)
void kv_gemm_tf32(const float* __restrict__ Wkv,
                  const float* __restrict__ X,
                  float* __restrict__ KVout)
{
    constexpr int M = 1024, N = 1024, K = 2048;
    __shared__ uint32_t As[2][16 * GLD];
    __shared__ uint32_t Bs[2][16 * GLD];

    const int tid  = threadIdx.x;
    const int lane = tid & 31;
    const int w    = tid >> 5;
    const int g    = lane >> 2;
    const int t    = lane & 3;
    const int m0w  = (w >> 1) * 32;
    const int n0w  = (w & 1) * 64;
    const int row0 = blockIdx.y * 128;
    const int col0 = blockIdx.x * 128;

    const float* Xb = X + (size_t)blockIdx.z * DIM * HW;
    float*       Cp = KVout + (size_t)blockIdx.z * M * N;

    const int ar = tid >> 1;
    const int ac = (tid & 1) * 8;
    const int br = tid >> 5;
    const int bc = (tid & 31) * 4;

    float a_regs[8];
    float b_regs[2][4];

    auto LDG = [&](int k0) {
        const float* ap = Wkv + (size_t)(row0 + ar) * K + k0 + ac;
        *reinterpret_cast<float4*>(&a_regs[0]) = *reinterpret_cast<const float4*>(ap);
        *reinterpret_cast<float4*>(&a_regs[4]) = *reinterpret_cast<const float4*>(ap + 4);
#pragma unroll
        for (int it = 0; it < 2; it++) {
            const int krow = k0 + br + it * 8;
            const int c  = krow >> 2;
            const int p  = (krow >> 1) & 1;
            const int qq = krow & 1;
            const float* xr = Xb + (size_t)c * HW + p * 64 + qq;
#pragma unroll
            for (int u = 0; u < 4; u++) {
                const int n = col0 + bc + u;
                b_regs[it][u] = xr[(n >> 5) * 128 + (n & 31) * 2];
            }
        }
    };
    auto STS = [&](int buf) {
#pragma unroll
        for (int j = 0; j < 8; j++)
            As[buf][(ac + j) * GLD + ar] = f2t(a_regs[j]);
#pragma unroll
        for (int it = 0; it < 2; it++) {
            uint4 u;
            u.x = f2t(b_regs[it][0]); u.y = f2t(b_regs[it][1]);
            u.z = f2t(b_regs[it][2]); u.w = f2t(b_regs[it][3]);
            *reinterpret_cast<uint4*>(&Bs[buf][(br + it * 8) * GLD + bc]) = u;
        }
    };

    float acc[2][8][4];
#pragma unroll
    for (int mt = 0; mt < 2; mt++)
#pragma unroll
        for (int nt = 0; nt < 8; nt++)
#pragma unroll
            for (int r = 0; r < 4; r++) acc[mt][nt][r] = 0.f;

    LDG(0);
    STS(0);
    __syncthreads();

    constexpr int NIT = K / 16;
    for (int i = 0; i < NIT; i++) {
        const int buf = i & 1;
        if (i + 1 < NIT) LDG((i + 1) * 16);

#pragma unroll
        for (int s = 0; s < 2; s++) {
            uint32_t a[2][4], b[8][2];
#pragma unroll
            for (int mt = 0; mt < 2; mt++) {
                const uint32_t* p0 = &As[buf][(s * 8 + t) * GLD + m0w + mt * 16 + g];
                const uint32_t* p1 = &As[buf][(s * 8 + t + 4) * GLD + m0w + mt * 16 + g];
                a[mt][0] = p0[0]; a[mt][1] = p0[8];
                a[mt][2] = p1[0]; a[mt][3] = p1[8];
            }
#pragma unroll
            for (int nt = 0; nt < 8; nt++) {
                b[nt][0] = Bs[buf][(s * 8 + t) * GLD + n0w + nt * 8 + g];
                b[nt][1] = Bs[buf][(s * 8 + t + 4) * GLD + n0w + nt * 8 + g];
            }
#pragma unroll
            for (int mt = 0; mt < 2; mt++)
#pragma unroll
                for (int nt = 0; nt < 8; nt++)
                    mma8(acc[mt][nt][0], acc[mt][nt][1], acc[mt][nt][2], acc[mt][nt][3],
                         a[mt][0], a[mt][1], a[mt][2], a[mt][3],
                         b[nt][0], b[nt][1]);
        }
        if (i + 1 < NIT) STS(buf ^ 1);
        __syncthreads();
    }

#pragma unroll
    for (int mt = 0; mt < 2; mt++)
#pragma unroll
        for (int nt = 0; nt < 8; nt++) {
            float* c0 = Cp + (size_t)(row0 + m0w + mt * 16 + g) * N
                           + col0 + n0w + nt * 8 + 2 * t;
            float2 v0; v0.x = acc[mt][nt][0]; v0.y = acc[mt][nt][1];
            float2 v1; v1.x = acc[mt][nt][2]; v1.y = acc[mt][nt][3];
            *reinterpret_cast<float2*>(c0)                 = v0;
            *reinterpret_cast<float2*>(c0 + 8 * (size_t)N) = v1;
        }
}

// ---------------------------------------------------------------------------
// Flash attention on tf32 tensor cores, register-resident P.
// 256 threads (8 warps), 128 queries/CTA, warp tile 16(i) x 128(j).
// Phase A K-columns permuted by pi(n)=(n&1)*4+(n>>1) so the S fragment is
// directly the phase-B A-operand (P never in smem). Smem 104 KB, 2 CTAs/SM.
// ---------------------------------------------------------------------------
#define ALD 136
#define ATTN_SMEM (3 * 64 * ALD * 4)

__global__ __launch_bounds__(256, 2)
void attn_tf32(const float* __restrict__ Q,
               const float* __restrict__ KV,
               float* __restrict__ Oout)
{
    const int bb = blockIdx.z;
    const int h  = blockIdx.y;
    const int i0 = blockIdx.x * 128;
    const int tid  = threadIdx.x;
    const int lane = tid & 31;
    const int w    = tid >> 5;            // 0..7
    const int g    = lane >> 2;
    const int t    = lane & 3;
    const int pg   = (g & 1) * 4 + (g >> 1);   // pi(g) column permutation
    const int r0w  = 16 * w;              // warp's query-row base

    const float* Qb = Q  + ((size_t)bb * DIM + h * DHEAD) * HW;
    const float* Kb = KV + ((size_t)bb * 2 * DIM + h * DHEAD) * LKV;
    const float* Vb = KV + ((size_t)bb * 2 * DIM + DIM + h * DHEAD) * LKV;
    float*       Ob = Oout + ((size_t)bb * DIM + h * DHEAD) * HW;

    extern __shared__ uint32_t sm[];
    uint32_t* Qs = sm;               // [64][136]
    uint32_t* Ks = Qs + 64 * ALD;    // [64][136]
    uint32_t* Vs = Ks + 64 * ALD;    // [64][136]

    const int ldd = tid >> 5;        // 0..7
    const int ldc = (tid & 31) * 4;

    // Load Q tile (scaled by 0.125, tf32)
#pragma unroll
    for (int it = 0; it < 8; it++) {
        const int d = ldd + it * 8;
        float4 v = *reinterpret_cast<const float4*>(Qb + (size_t)d * HW + i0 + ldc);
        uint4 u;
        u.x = f2t(v.x * 0.125f); u.y = f2t(v.y * 0.125f);
        u.z = f2t(v.z * 0.125f); u.w = f2t(v.w * 0.125f);
        *reinterpret_cast<uint4*>(&Qs[d * ALD + ldc]) = u;
    }

    float o[8][4];
#pragma unroll
    for (int nt = 0; nt < 8; nt++)
#pragma unroll
        for (int r = 0; r < 4; r++) o[nt][r] = 0.f;

    float mrow[2], lrow[2];
#pragma unroll
    for (int r = 0; r < 2; r++) { mrow[r] = -1e30f; lrow[r] = 0.f; }

    for (int j0 = 0; j0 < LKV; j0 += 128) {
        __syncthreads();
#pragma unroll
        for (int it = 0; it < 8; it++) {
            const int d = ldd + it * 8;
            float4 kv4 = *reinterpret_cast<const float4*>(Kb + (size_t)d * LKV + j0 + ldc);
            uint4 uk;
            uk.x = f2t(kv4.x); uk.y = f2t(kv4.y); uk.z = f2t(kv4.z); uk.w = f2t(kv4.w);
            *reinterpret_cast<uint4*>(&Ks[d * ALD + ldc]) = uk;
            float4 vv4 = *reinterpret_cast<const float4*>(Vb + (size_t)d * LKV + j0 + ldc);
            uint4 uv;
            uv.x = f2t(vv4.x); uv.y = f2t(vv4.y); uv.z = f2t(vv4.z); uv.w = f2t(vv4.w);
            *reinterpret_cast<uint4*>(&Vs[d * ALD + ldc]) = uv;
        }
        __syncthreads();

        // ---- Phase A: S = Q^T K (K columns permuted by pi) ----
        float s[16][4];
#pragma unroll
        for (int nt = 0; nt < 16; nt++)
#pragma unroll
            for (int r = 0; r < 4; r++) s[nt][r] = 0.f;

#pragma unroll
        for (int ks = 0; ks < 8; ks++) {
            const uint32_t* p0 = &Qs[(ks * 8 + t) * ALD + r0w + g];
            const uint32_t* p1 = &Qs[(ks * 8 + t + 4) * ALD + r0w + g];
            uint32_t a0 = p0[0], a1 = p0[8], a2 = p1[0], a3 = p1[8];
#pragma unroll
            for (int nt = 0; nt < 16; nt++) {
                uint32_t b0 = Ks[(ks * 8 + t) * ALD + nt * 8 + pg];
                uint32_t b1 = Ks[(ks * 8 + t + 4) * ALD + nt * 8 + pg];
                mma8(s[nt][0], s[nt][1], s[nt][2], s[nt][3],
                     a0, a1, a2, a3, b0, b1);
            }
        }

        // ---- Online softmax (regs {0,1}=row g, {2,3}=row g+8) ----
        float fac[2];
#pragma unroll
        for (int hh = 0; hh < 2; hh++) {
            float mx = -1e30f;
#pragma unroll
            for (int nt = 0; nt < 16; nt++) {
                mx = fmaxf(mx, s[nt][2 * hh]);
                mx = fmaxf(mx, s[nt][2 * hh + 1]);
            }
            mx = fmaxf(mx, __shfl_xor_sync(0xffffffffu, mx, 1));
            mx = fmaxf(mx, __shfl_xor_sync(0xffffffffu, mx, 2));
            const float mn = fmaxf(mrow[hh], mx);
            fac[hh] = __expf(mrow[hh] - mn);
            mrow[hh] = mn;
            float ls = 0.f;
#pragma unroll
            for (int nt = 0; nt < 16; nt++) {
                const float p0 = __expf(s[nt][2 * hh]     - mn);
                const float p1 = __expf(s[nt][2 * hh + 1] - mn);
                s[nt][2 * hh]     = p0;
                s[nt][2 * hh + 1] = p1;
                ls += p0 + p1;
            }
            lrow[hh] = lrow[hh] * fac[hh] + ls;
        }

        // Rescale O accumulators; convert P to tf32 in registers
#pragma unroll
        for (int nt = 0; nt < 8; nt++) {
            o[nt][0] *= fac[0];
            o[nt][1] *= fac[0];
            o[nt][2] *= fac[1];
            o[nt][3] *= fac[1];
        }
#pragma unroll
        for (int nt = 0; nt < 16; nt++)
#pragma unroll
            for (int r = 0; r < 4; r++)
                s[nt][r] = __uint_as_float(f2t(s[nt][r]));

        // ---- Phase B: O += P @ V^T (P from registers) ----
#pragma unroll
        for (int ks = 0; ks < 16; ks++) {
            uint32_t a0 = __float_as_uint(s[ks][0]);
            uint32_t a1 = __float_as_uint(s[ks][2]);
            uint32_t a2 = __float_as_uint(s[ks][1]);
            uint32_t a3 = __float_as_uint(s[ks][3]);
#pragma unroll
            for (int nt = 0; nt < 8; nt++) {
                uint32_t b0 = Vs[(nt * 8 + g) * ALD + ks * 8 + t];
                uint32_t b1 = Vs[(nt * 8 + g) * ALD + ks * 8 + t + 4];
                mma8(o[nt][0], o[nt][1], o[nt][2], o[nt][3],
                     a0, a1, a2, a3, b0, b1);
            }
        }
    }

    // Final l reduction across the 4 t-lanes
    float inv[2];
#pragma unroll
    for (int idx = 0; idx < 2; idx++) {
        float ls = lrow[idx];
        ls += __shfl_xor_sync(0xffffffffu, ls, 1);
        ls += __shfl_xor_sync(0xffffffffu, ls, 2);
        inv[idx] = 1.f / ls;
    }

    // Stage O^T [d][i] in smem (reuse Qs region), then coalesced store
    __syncthreads();
    float* Of = reinterpret_cast<float*>(Qs);
    {
        const int row = r0w + g;
#pragma unroll
        for (int nt = 0; nt < 8; nt++) {
            const int d = nt * 8 + 2 * t;
            Of[d * ALD + row]           = o[nt][0] * inv[0];
            Of[(d + 1) * ALD + row]     = o[nt][1] * inv[0];
            Of[d * ALD + row + 8]       = o[nt][2] * inv[1];
            Of[(d + 1) * ALD + row + 8] = o[nt][3] * inv[1];
        }
    }
    __syncthreads();

#pragma unroll
    for (int it = 0; it < 8; it++) {
        const int d = ldd + it * 8;
        *reinterpret_cast<float4*>(Ob + (size_t)d * HW + i0 + ldc) =
            *reinterpret_cast<const float4*>(&Of[d * ALD + ldc]);
    }
}

// ---------------------------------------------------------------------------
// Launch
// ---------------------------------------------------------------------------
extern "C" void kernel_launch(void* const* d_in, const int* in_sizes, int n_in,
                              void* d_out, int out_size)
{
    const float* x    = (const float*)d_in[0];   // [4,512,64,64]
    const float* wq   = (const float*)d_in[1];   // [512,512,1,1]
    const float* wkv  = (const float*)d_in[2];   // [1024,512,2,2]
    const float* wout = (const float*)d_in[3];   // [512,512,1,1]
    float* out = (float*)d_out;                  // [4,512,64,64]

    float *qbuf, *kvbuf, *obuf;
    cudaGetSymbolAddress((void**)&qbuf,  g_q);
    cudaGetSymbolAddress((void**)&kvbuf, g_kv);
    cudaGetSymbolAddress((void**)&obuf,  g_o);

    cudaFuncSetAttribute(attn_tf32,
                         cudaFuncAttributeMaxDynamicSharedMemorySize, ATTN_SMEM);

    // Q = Wq @ X : M=512, N=4096, K=512
    gemm_tf32<512, 4096, 512><<<dim3(32, 4, BATCH), 256>>>(wq, x, qbuf);

    // KV = Wkv @ im2col(X) : M=1024, N=1024, K=2048
    kv_gemm_tf32<<<dim3(8, 8, BATCH), 256>>>(wkv, x, kvbuf);

    // Fused attention
    attn_tf32<<<dim3(HW / 128, HEADS, BATCH), 256, ATTN_SMEM>>>(qbuf, kvbuf, obuf);

    // Y = Wout @ O
    gemm_tf32<512, 4096, 512><<<dim3(32, 4, BATCH), 256>>>(wout, obuf, out);
}

// round 7
// speedup vs baseline: 1.0005x; 1.0005x over previous
#include <cuda_runtime.h>
#include <cstdint>

// Problem constants
#define BATCH 4
#define DIM   512
#define HEADS 8
#define DHEAD 64
#define HW    4096   // 64*64 query positions
#define LKV   1024   // 32*32 kv positions

// Scratch (device globals; allocation-free per harness rules)
__device__ float g_q [BATCH * DIM * HW];        // Q  [b][hd][s]
__device__ float g_kv[BATCH * 2 * DIM * LKV];   // KV [b][o][ij]
__device__ float g_o [BATCH * DIM * HW];        // attn out

// ---------------------------------------------------------------------------
// tf32 helpers
// ---------------------------------------------------------------------------
__device__ __forceinline__ uint32_t f2t(float f) {
    uint32_t u;
    asm("cvt.rna.tf32.f32 %0, %1;" : "=r"(u) : "f"(f));
    return u;
}

__device__ __forceinline__ void mma8(float& d0, float& d1, float& d2, float& d3,
                                     uint32_t a0, uint32_t a1, uint32_t a2, uint32_t a3,
                                     uint32_t b0, uint32_t b1) {
    asm("mma.sync.aligned.m16n8k8.row.col.f32.tf32.tf32.f32 "
        "{%0,%1,%2,%3},{%4,%5,%6,%7},{%8,%9},{%0,%1,%2,%3};"
        : "+f"(d0), "+f"(d1), "+f"(d2), "+f"(d3)
        : "r"(a0), "r"(a1), "r"(a2), "r"(a3), "r"(b0), "r"(b1));
}

// ---------------------------------------------------------------------------
// tf32 tensor-core GEMM, 256 threads (8 warps), warp tile 32x64.
// C[b] = A @ B[b]; A [M,K] row-major shared; B [K,N] batched; C [M,N].
// CTA 128x128, BK=16, double-buffered smem + register prefetch.
// ---------------------------------------------------------------------------
#define GLD 136

template <int M, int N, int K>
__global__ __launch_bounds__(256, 2)
void gemm_tf32(const float* __restrict__ A,
               const float* __restrict__ Bsrc,
               float* __restrict__ Csrc)
{
    __shared__ uint32_t As[2][16 * GLD];
    __shared__ uint32_t Bs[2][16 * GLD];

    const int tid  = threadIdx.x;
    const int lane = tid & 31;
    const int w    = tid >> 5;          // 0..7
    const int g    = lane >> 2;
    const int t    = lane & 3;
    const int m0w  = (w >> 1) * 32;     // 4 warp-rows of 32
    const int n0w  = (w & 1) * 64;      // 2 warp-cols of 64
    const int row0 = blockIdx.y * 128;
    const int col0 = blockIdx.x * 128;

    const float* Bp = Bsrc + (size_t)blockIdx.z * K * N;
    float*       Cp = Csrc + (size_t)blockIdx.z * M * N;

    const int ar = tid >> 1;            // 0..127
    const int ac = (tid & 1) * 8;       // 0 or 8
    const int br = tid >> 5;            // 0..7 (+8)
    const int bc = (tid & 31) * 4;

    float a_regs[8];
    float4 b_regs[2];

    auto LDG = [&](int k0) {
        const float* ap = A + (size_t)(row0 + ar) * K + k0 + ac;
        *reinterpret_cast<float4*>(&a_regs[0]) = *reinterpret_cast<const float4*>(ap);
        *reinterpret_cast<float4*>(&a_regs[4]) = *reinterpret_cast<const float4*>(ap + 4);
#pragma unroll
        for (int it = 0; it < 2; it++)
            b_regs[it] = *reinterpret_cast<const float4*>(
                Bp + (size_t)(k0 + br + it * 8) * N + col0 + bc);
    };
    auto STS = [&](int buf) {
#pragma unroll
        for (int j = 0; j < 8; j++)
            As[buf][(ac + j) * GLD + ar] = f2t(a_regs[j]);
#pragma unroll
        for (int it = 0; it < 2; it++) {
            uint4 u;
            u.x = f2t(b_regs[it].x); u.y = f2t(b_regs[it].y);
            u.z = f2t(b_regs[it].z); u.w = f2t(b_regs[it].w);
            *reinterpret_cast<uint4*>(&Bs[buf][(br + it * 8) * GLD + bc]) = u;
        }
    };

    float acc[2][8][4];
#pragma unroll
    for (int mt = 0; mt < 2; mt++)
#pragma unroll
        for (int nt = 0; nt < 8; nt++)
#pragma unroll
            for (int r = 0; r < 4; r++) acc[mt][nt][r] = 0.f;

    LDG(0);
    STS(0);
    __syncthreads();

    constexpr int NIT = K / 16;
    for (int i = 0; i < NIT; i++) {
        const int buf = i & 1;
        if (i + 1 < NIT) LDG((i + 1) * 16);

#pragma unroll
        for (int s = 0; s < 2; s++) {
            uint32_t a[2][4], b[8][2];
#pragma unroll
            for (int mt = 0; mt < 2; mt++) {
                const uint32_t* p0 = &As[buf][(s * 8 + t) * GLD + m0w + mt * 16 + g];
                const uint32_t* p1 = &As[buf][(s * 8 + t + 4) * GLD + m0w + mt * 16 + g];
                a[mt][0] = p0[0]; a[mt][1] = p0[8];
                a[mt][2] = p1[0]; a[mt][3] = p1[8];
            }
#pragma unroll
            for (int nt = 0; nt < 8; nt++) {
                b[nt][0] = Bs[buf][(s * 8 + t) * GLD + n0w + nt * 8 + g];
                b[nt][1] = Bs[buf][(s * 8 + t + 4) * GLD + n0w + nt * 8 + g];
            }
#pragma unroll
            for (int mt = 0; mt < 2; mt++)
#pragma unroll
                for (int nt = 0; nt < 8; nt++)
                    mma8(acc[mt][nt][0], acc[mt][nt][1], acc[mt][nt][2], acc[mt][nt][3],
                         a[mt][0], a[mt][1], a[mt][2], a[mt][3],
                         b[nt][0], b[nt][1]);
        }
        if (i + 1 < NIT) STS(buf ^ 1);
        __syncthreads();
    }

#pragma unroll
    for (int mt = 0; mt < 2; mt++)
#pragma unroll
        for (int nt = 0; nt < 8; nt++) {
            float* c0 = Cp + (size_t)(row0 + m0w + mt * 16 + g) * N
                           + col0 + n0w + nt * 8 + 2 * t;
            float2 v0; v0.x = acc[mt][nt][0]; v0.y = acc[mt][nt][1];
            float2 v1; v1.x = acc[mt][nt][2]; v1.y = acc[mt][nt][3];
            *reinterpret_cast<float2*>(c0)                 = v0;
            *reinterpret_cast<float2*>(c0 + 8 * (size_t)N) = v1;
        }
}

// ---------------------------------------------------------------------------
// KV conv as implicit-im2col tf32 GEMM, same 256-thread tiling.
// M=1024, N=1024, K=2048. k = c*4 + p*2 + q; n = i*32 + j.
// ---------------------------------------------------------------------------
__global__ __launch_bounds__(256, 2)
void kv_gemm_tf32(const float* __restrict__ Wkv,
                  const float* __restrict__ X,
                  float* __restrict__ KVout)
{
    constexpr int M = 1024, N = 1024, K = 2048;
    __shared__ uint32_t As[2][16 * GLD];
    __shared__ uint32_t Bs[2][16 * GLD];

    const int tid  = threadIdx.x;
    const int lane = tid & 31;
    const int w    = tid >> 5;
    const int g    = lane >> 2;
    const int t    = lane & 3;
    const int m0w  = (w >> 1) * 32;
    const int n0w  = (w & 1) * 64;
    const int row0 = blockIdx.y * 128;
    const int col0 = blockIdx.x * 128;

    const float* Xb = X + (size_t)blockIdx.z * DIM * HW;
    float*       Cp = KVout + (size_t)blockIdx.z * M * N;

    const int ar = tid >> 1;
    const int ac = (tid & 1) * 8;
    const int br = tid >> 5;
    const int bc = (tid & 31) * 4;

    float a_regs[8];
    float b_regs[2][4];

    auto LDG = [&](int k0) {
        const float* ap = Wkv + (size_t)(row0 + ar) * K + k0 + ac;
        *reinterpret_cast<float4*>(&a_regs[0]) = *reinterpret_cast<const float4*>(ap);
        *reinterpret_cast<float4*>(&a_regs[4]) = *reinterpret_cast<const float4*>(ap + 4);
#pragma unroll
        for (int it = 0; it < 2; it++) {
            const int krow = k0 + br + it * 8;
            const int c  = krow >> 2;
            const int p  = (krow >> 1) & 1;
            const int qq = krow & 1;
            const float* xr = Xb + (size_t)c * HW + p * 64 + qq;
#pragma unroll
            for (int u = 0; u < 4; u++) {
                const int n = col0 + bc + u;
                b_regs[it][u] = xr[(n >> 5) * 128 + (n & 31) * 2];
            }
        }
    };
    auto STS = [&](int buf) {
#pragma unroll
        for (int j = 0; j < 8; j++)
            As[buf][(ac + j) * GLD + ar] = f2t(a_regs[j]);
#pragma unroll
        for (int it = 0; it < 2; it++) {
            uint4 u;
            u.x = f2t(b_regs[it][0]); u.y = f2t(b_regs[it][1]);
            u.z = f2t(b_regs[it][2]); u.w = f2t(b_regs[it][3]);
            *reinterpret_cast<uint4*>(&Bs[buf][(br + it * 8) * GLD + bc]) = u;
        }
    };

    float acc[2][8][4];
#pragma unroll
    for (int mt = 0; mt < 2; mt++)
#pragma unroll
        for (int nt = 0; nt < 8; nt++)
#pragma unroll
            for (int r = 0; r < 4; r++) acc[mt][nt][r] = 0.f;

    LDG(0);
    STS(0);
    __syncthreads();

    constexpr int NIT = K / 16;
    for (int i = 0; i < NIT; i++) {
        const int buf = i & 1;
        if (i + 1 < NIT) LDG((i + 1) * 16);

#pragma unroll
        for (int s = 0; s < 2; s++) {
            uint32_t a[2][4], b[8][2];
#pragma unroll
            for (int mt = 0; mt < 2; mt++) {
                const uint32_t* p0 = &As[buf][(s * 8 + t) * GLD + m0w + mt * 16 + g];
                const uint32_t* p1 = &As[buf][(s * 8 + t + 4) * GLD + m0w + mt * 16 + g];
                a[mt][0] = p0[0]; a[mt][1] = p0[8];
                a[mt][2] = p1[0]; a[mt][3] = p1[8];
            }
#pragma unroll
            for (int nt = 0; nt < 8; nt++) {
                b[nt][0] = Bs[buf][(s * 8 + t) * GLD + n0w + nt * 8 + g];
                b[nt][1] = Bs[buf][(s * 8 + t + 4) * GLD + n0w + nt * 8 + g];
            }
#pragma unroll
            for (int mt = 0; mt < 2; mt++)
#pragma unroll
                for (int nt = 0; nt < 8; nt++)
                    mma8(acc[mt][nt][0], acc[mt][nt][1], acc[mt][nt][2], acc[mt][nt][3],
                         a[mt][0], a[mt][1], a[mt][2], a[mt][3],
                         b[nt][0], b[nt][1]);
        }
        if (i + 1 < NIT) STS(buf ^ 1);
        __syncthreads();
    }

#pragma unroll
    for (int mt = 0; mt < 2; mt++)
#pragma unroll
        for (int nt = 0; nt < 8; nt++) {
            float* c0 = Cp + (size_t)(row0 + m0w + mt * 16 + g) * N
                           + col0 + n0w + nt * 8 + 2 * t;
            float2 v0; v0.x = acc[mt][nt][0]; v0.y = acc[mt][nt][1];
            float2 v1; v1.x = acc[mt][nt][2]; v1.y = acc[mt][nt][3];
            *reinterpret_cast<float2*>(c0)                 = v0;
            *reinterpret_cast<float2*>(c0 + 8 * (size_t)N) = v1;
        }
}

// ---------------------------------------------------------------------------
// Flash attention on tf32 tensor cores, register-resident P.
// 256 threads (8 warps), 128 queries/CTA, warp tile 16(i) x 128(j).
// Phase A K-columns permuted by pi(n)=(n&1)*4+(n>>1) so the S fragment is
// directly the phase-B A-operand (P never in smem). Smem 104 KB, 2 CTAs/SM.
// ---------------------------------------------------------------------------
#define ALD 136
#define ATTN_SMEM (3 * 64 * ALD * 4)

__global__ __launch_bounds__(256, 2)
void attn_tf32(const float* __restrict__ Q,
               const float* __restrict__ KV,
               float* __restrict__ Oout)
{
    const int bb = blockIdx.z;
    const int h  = blockIdx.y;
    const int i0 = blockIdx.x * 128;
    const int tid  = threadIdx.x;
    const int lane = tid & 31;
    const int w    = tid >> 5;            // 0..7
    const int g    = lane >> 2;
    const int t    = lane & 3;
    const int pg   = (g & 1) * 4 + (g >> 1);   // pi(g) column permutation
    const int r0w  = 16 * w;              // warp's query-row base

    const float* Qb = Q  + ((size_t)bb * DIM + h * DHEAD) * HW;
    const float* Kb = KV + ((size_t)bb * 2 * DIM + h * DHEAD) * LKV;
    const float* Vb = KV + ((size_t)bb * 2 * DIM + DIM + h * DHEAD) * LKV;
    float*       Ob = Oout + ((size_t)bb * DIM + h * DHEAD) * HW;

    extern __shared__ uint32_t sm[];
    uint32_t* Qs = sm;               // [64][136]
    uint32_t* Ks = Qs + 64 * ALD;    // [64][136]
    uint32_t* Vs = Ks + 64 * ALD;    // [64][136]

    const int ldd = tid >> 5;        // 0..7
    const int ldc = (tid & 31) * 4;

    // Load Q tile (scaled by 0.125, tf32)
#pragma unroll
    for (int it = 0; it < 8; it++) {
        const int d = ldd + it * 8;
        float4 v = *reinterpret_cast<const float4*>(Qb + (size_t)d * HW + i0 + ldc);
        uint4 u;
        u.x = f2t(v.x * 0.125f); u.y = f2t(v.y * 0.125f);
        u.z = f2t(v.z * 0.125f); u.w = f2t(v.w * 0.125f);
        *reinterpret_cast<uint4*>(&Qs[d * ALD + ldc]) = u;
    }

    float o[8][4];
#pragma unroll
    for (int nt = 0; nt < 8; nt++)
#pragma unroll
        for (int r = 0; r < 4; r++) o[nt][r] = 0.f;

    float mrow[2], lrow[2];
#pragma unroll
    for (int r = 0; r < 2; r++) { mrow[r] = -1e30f; lrow[r] = 0.f; }

    for (int j0 = 0; j0 < LKV; j0 += 128) {
        __syncthreads();
#pragma unroll
        for (int it = 0; it < 8; it++) {
            const int d = ldd + it * 8;
            float4 kv4 = *reinterpret_cast<const float4*>(Kb + (size_t)d * LKV + j0 + ldc);
            uint4 uk;
            uk.x = f2t(kv4.x); uk.y = f2t(kv4.y); uk.z = f2t(kv4.z); uk.w = f2t(kv4.w);
            *reinterpret_cast<uint4*>(&Ks[d * ALD + ldc]) = uk;
            float4 vv4 = *reinterpret_cast<const float4*>(Vb + (size_t)d * LKV + j0 + ldc);
            uint4 uv;
            uv.x = f2t(vv4.x); uv.y = f2t(vv4.y); uv.z = f2t(vv4.z); uv.w = f2t(vv4.w);
            *reinterpret_cast<uint4*>(&Vs[d * ALD + ldc]) = uv;
        }
        __syncthreads();

        // ---- Phase A: S = Q^T K (K columns permuted by pi) ----
        float s[16][4];
#pragma unroll
        for (int nt = 0; nt < 16; nt++)
#pragma unroll
            for (int r = 0; r < 4; r++) s[nt][r] = 0.f;

#pragma unroll
        for (int ks = 0; ks < 8; ks++) {
            const uint32_t* p0 = &Qs[(ks * 8 + t) * ALD + r0w + g];
            const uint32_t* p1 = &Qs[(ks * 8 + t + 4) * ALD + r0w + g];
            uint32_t a0 = p0[0], a1 = p0[8], a2 = p1[0], a3 = p1[8];
#pragma unroll
            for (int nt = 0; nt < 16; nt++) {
                uint32_t b0 = Ks[(ks * 8 + t) * ALD + nt * 8 + pg];
                uint32_t b1 = Ks[(ks * 8 + t + 4) * ALD + nt * 8 + pg];
                mma8(s[nt][0], s[nt][1], s[nt][2], s[nt][3],
                     a0, a1, a2, a3, b0, b1);
            }
        }

        // ---- Online softmax (regs {0,1}=row g, {2,3}=row g+8) ----
        float fac[2];
#pragma unroll
        for (int hh = 0; hh < 2; hh++) {
            float mx = -1e30f;
#pragma unroll
            for (int nt = 0; nt < 16; nt++) {
                mx = fmaxf(mx, s[nt][2 * hh]);
                mx = fmaxf(mx, s[nt][2 * hh + 1]);
            }
            mx = fmaxf(mx, __shfl_xor_sync(0xffffffffu, mx, 1));
            mx = fmaxf(mx, __shfl_xor_sync(0xffffffffu, mx, 2));
            const float mn = fmaxf(mrow[hh], mx);
            fac[hh] = __expf(mrow[hh] - mn);
            mrow[hh] = mn;
            float ls = 0.f;
#pragma unroll
            for (int nt = 0; nt < 16; nt++) {
                const float p0 = __expf(s[nt][2 * hh]     - mn);
                const float p1 = __expf(s[nt][2 * hh + 1] - mn);
                s[nt][2 * hh]     = p0;
                s[nt][2 * hh + 1] = p1;
                ls += p0 + p1;
            }
            lrow[hh] = lrow[hh] * fac[hh] + ls;
        }

        // Rescale O accumulators; convert P to tf32 in registers
#pragma unroll
        for (int nt = 0; nt < 8; nt++) {
            o[nt][0] *= fac[0];
            o[nt][1] *= fac[0];
            o[nt][2] *= fac[1];
            o[nt][3] *= fac[1];
        }
#pragma unroll
        for (int nt = 0; nt < 16; nt++)
#pragma unroll
            for (int r = 0; r < 4; r++)
                s[nt][r] = __uint_as_float(f2t(s[nt][r]));

        // ---- Phase B: O += P @ V^T (P from registers) ----
#pragma unroll
        for (int ks = 0; ks < 16; ks++) {
            uint32_t a0 = __float_as_uint(s[ks][0]);
            uint32_t a1 = __float_as_uint(s[ks][2]);
            uint32_t a2 = __float_as_uint(s[ks][1]);
            uint32_t a3 = __float_as_uint(s[ks][3]);
#pragma unroll
            for (int nt = 0; nt < 8; nt++) {
                uint32_t b0 = Vs[(nt * 8 + g) * ALD + ks * 8 + t];
                uint32_t b1 = Vs[(nt * 8 + g) * ALD + ks * 8 + t + 4];
                mma8(o[nt][0], o[nt][1], o[nt][2], o[nt][3],
                     a0, a1, a2, a3, b0, b1);
            }
        }
    }

    // Final l reduction across the 4 t-lanes
    float inv[2];
#pragma unroll
    for (int idx = 0; idx < 2; idx++) {
        float ls = lrow[idx];
        ls += __shfl_xor_sync(0xffffffffu, ls, 1);
        ls += __shfl_xor_sync(0xffffffffu, ls, 2);
        inv[idx] = 1.f / ls;
    }

    // Stage O^T [d][i] in smem (reuse Qs region), then coalesced store
    __syncthreads();
    float* Of = reinterpret_cast<float*>(Qs);
    {
        const int row = r0w + g;
#pragma unroll
        for (int nt = 0; nt < 8; nt++) {
            const int d = nt * 8 + 2 * t;
            Of[d * ALD + row]           = o[nt][0] * inv[0];
            Of[(d + 1) * ALD + row]     = o[nt][1] * inv[0];
            Of[d * ALD + row + 8]       = o[nt][2] * inv[1];
            Of[(d + 1) * ALD + row + 8] = o[nt][3] * inv[1];
        }
    }
    __syncthreads();

#pragma unroll
    for (int it = 0; it < 8; it++) {
        const int d = ldd + it * 8;
        *reinterpret_cast<float4*>(Ob + (size_t)d * HW + i0 + ldc) =
            *reinterpret_cast<const float4*>(&Of[d * ALD + ldc]);
    }
}

// ---------------------------------------------------------------------------
// Launch
// ---------------------------------------------------------------------------
extern "C" void kernel_launch(void* const* d_in, const int* in_sizes, int n_in,
                              void* d_out, int out_size)
{
    const float* x    = (const float*)d_in[0];   // [4,512,64,64]
    const float* wq   = (const float*)d_in[1];   // [512,512,1,1]
    const float* wkv  = (const float*)d_in[2];   // [1024,512,2,2]
    const float* wout = (const float*)d_in[3];   // [512,512,1,1]
    float* out = (float*)d_out;                  // [4,512,64,64]

    float *qbuf, *kvbuf, *obuf;
    cudaGetSymbolAddress((void**)&qbuf,  g_q);
    cudaGetSymbolAddress((void**)&kvbuf, g_kv);
    cudaGetSymbolAddress((void**)&obuf,  g_o);

    cudaFuncSetAttribute(attn_tf32,
                         cudaFuncAttributeMaxDynamicSharedMemorySize, ATTN_SMEM);

    // Q = Wq @ X : M=512, N=4096, K=512
    gemm_tf32<512, 4096, 512><<<dim3(32, 4, BATCH), 256>>>(wq, x, qbuf);

    // KV = Wkv @ im2col(X) : M=1024, N=1024, K=2048
    kv_gemm_tf32<<<dim3(8, 8, BATCH), 256>>>(wkv, x, kvbuf);

    // Fused attention
    attn_tf32<<<dim3(HW / 128, HEADS, BATCH), 256, ATTN_SMEM>>>(qbuf, kvbuf, obuf);

    // Y = Wout @ O
    gemm_tf32<512, 4096, 512><<<dim3(32, 4, BATCH), 256>>>(wout, obuf, out);
}

// round 9
// speedup vs baseline: 1.7947x; 1.7938x over previous
#include <cuda_runtime.h>
#include <cuda_fp16.h>
#include <cstdint>

#define BATCH 4
#define DIM   512
#define HEADS 8
#define DHEAD 64
#define HW    4096
#define LKV   1024

// fp16 intermediates (device globals; allocation-free)
__device__ __half g_q [BATCH * DIM * HW];        // Q  [b][ch][pos]
__device__ __half g_kv[BATCH * 2 * DIM * LKV];   // KV [b][och][ij]
__device__ __half g_o [BATCH * DIM * HW];        // attn out [b][ch][pos]

// ---------------- helpers ----------------
__device__ __forceinline__ uint32_t packh2(float lo, float hi) {
    uint32_t r;
    asm("cvt.rn.f16x2.f32 %0, %1, %2;" : "=r"(r) : "f"(hi), "f"(lo));
    return r;
}
__device__ __forceinline__ uint32_t smem_u32(const void* p) {
    uint32_t a;
    asm("{ .reg .u64 t; cvta.to.shared.u64 t, %1; cvt.u32.u64 %0, t; }" : "=r"(a) : "l"(p));
    return a;
}
__device__ __forceinline__ void ldsm4(uint32_t& r0, uint32_t& r1, uint32_t& r2, uint32_t& r3,
                                      uint32_t addr) {
    asm volatile("ldmatrix.sync.aligned.m8n8.x4.shared.b16 {%0,%1,%2,%3}, [%4];"
                 : "=r"(r0), "=r"(r1), "=r"(r2), "=r"(r3) : "r"(addr));
}
__device__ __forceinline__ void ldsm4t(uint32_t& r0, uint32_t& r1, uint32_t& r2, uint32_t& r3,
                                       uint32_t addr) {
    asm volatile("ldmatrix.sync.aligned.m8n8.x4.trans.shared.b16 {%0,%1,%2,%3}, [%4];"
                 : "=r"(r0), "=r"(r1), "=r"(r2), "=r"(r3) : "r"(addr));
}
__device__ __forceinline__ void mma16(float* d, const uint32_t* a, uint32_t b0, uint32_t b1) {
    asm volatile("mma.sync.aligned.m16n8k16.row.col.f32.f16.f16.f32 "
        "{%0,%1,%2,%3},{%4,%5,%6,%7},{%8,%9},{%0,%1,%2,%3};"
        : "+f"(d[0]), "+f"(d[1]), "+f"(d[2]), "+f"(d[3])
        : "r"(a[0]), "r"(a[1]), "r"(a[2]), "r"(a[3]), "r"(b0), "r"(b1));
}

// ---------------------------------------------------------------------------
// fp16 tensor-core GEMM via ldmatrix. C[b] = A @ B[b].
// A [M,K] fp32 row-major weights. B modes:
//   0: fp32 [K,N] batched (x as-is)    1: im2col of x (fp32)    2: half [K,N]
// 128 thr, 4 warps, warp tile 64x64 (mt=4, nt=8), BK=32, double-buffered.
// As: [m][k] halves, row stride 40. Bs: [k][n] halves, row stride 136.
// ---------------------------------------------------------------------------
template <int M, int N, int K, int BMODE, bool OUTF32, bool SCALEA>
__global__ __launch_bounds__(128)
void gemm_f16(const float* __restrict__ A, const void* __restrict__ Bv,
              void* __restrict__ Cv)
{
    __shared__ __half As[2][128 * 40];
    __shared__ __half Bs[2][32 * 136];

    const int tid = threadIdx.x, lane = tid & 31, w = tid >> 5;
    const int g = lane >> 2, t = lane & 3;
    const int lr = lane & 7, lb3 = (lane >> 3) & 1, lb4 = (lane >> 4) & 1;
    const int m0w = (w >> 1) * 64, n0w = (w & 1) * 64;
    const int row0 = blockIdx.y * 128, col0 = blockIdx.x * 128;
    const int z = blockIdx.z;

    const float* Bf = (const float*)Bv;
    const __half* Bh = (const __half*)Bv;

    uint32_t aBase[2] = { smem_u32(&As[0][0]), smem_u32(&As[1][0]) };
    uint32_t bBase[2] = { smem_u32(&Bs[0][0]), smem_u32(&Bs[1][0]) };

    float a_f[32];
    float b_f[32];
    uint4 b_u[4];

    auto LDGA = [&](int k0) {
        const float* ap = A + (size_t)(row0 + tid) * K + k0;
#pragma unroll
        for (int u = 0; u < 8; u++)
            *reinterpret_cast<float4*>(&a_f[u * 4]) =
                *reinterpret_cast<const float4*>(ap + u * 4);
    };
    auto STSA = [&](int buf) {
        uint32_t h[16];
#pragma unroll
        for (int u = 0; u < 16; u++) {
            float x0 = a_f[u * 2], x1 = a_f[u * 2 + 1];
            if (SCALEA) { x0 *= 0.125f; x1 *= 0.125f; }
            h[u] = packh2(x0, x1);
        }
        uint4* dst = reinterpret_cast<uint4*>(&As[buf][tid * 40]);
        dst[0] = make_uint4(h[0], h[1], h[2], h[3]);
        dst[1] = make_uint4(h[4], h[5], h[6], h[7]);
        dst[2] = make_uint4(h[8], h[9], h[10], h[11]);
        dst[3] = make_uint4(h[12], h[13], h[14], h[15]);
    };
    auto LDGB = [&](int k0) {
        if (BMODE == 0) {
            const int kr = tid >> 2, nb = (tid & 3) * 32;
            const float* bp = Bf + (size_t)z * K * N + (size_t)(k0 + kr) * N + col0 + nb;
#pragma unroll
            for (int u = 0; u < 8; u++)
                *reinterpret_cast<float4*>(&b_f[u * 4]) =
                    *reinterpret_cast<const float4*>(bp + u * 4);
        } else if (BMODE == 1) {
            const int cp = tid >> 4, rem = tid & 15;
            const int i0b = col0 >> 5;
            const float* Xb = Bf + (size_t)z * DIM * HW;
            const int c = (k0 >> 2) + cp;
#pragma unroll
            for (int it = 0; it < 8; it++) {
                const int ir = it >> 1, p = it & 1;
                *reinterpret_cast<float4*>(&b_f[it * 4]) =
                    *reinterpret_cast<const float4*>(
                        Xb + (size_t)c * HW + (2 * (i0b + ir) + p) * 64 + 4 * rem);
            }
        } else {
#pragma unroll
            for (int it = 0; it < 4; it++) {
                const int row = (tid >> 4) + it * 8, col = (tid & 15) * 8;
                b_u[it] = *reinterpret_cast<const uint4*>(
                    Bh + (size_t)z * K * N + (size_t)(k0 + row) * N + col0 + col);
            }
        }
    };
    auto STSB = [&](int buf) {
        if (BMODE == 0) {
            const int kr = tid >> 2, nb = (tid & 3) * 32;
#pragma unroll
            for (int u = 0; u < 8; u++) {
                uint32_t h0 = packh2(b_f[u * 4 + 0], b_f[u * 4 + 1]);
                uint32_t h1 = packh2(b_f[u * 4 + 2], b_f[u * 4 + 3]);
                *reinterpret_cast<uint2*>(&Bs[buf][kr * 136 + nb + u * 4]) = make_uint2(h0, h1);
            }
        } else if (BMODE == 1) {
            const int cp = tid >> 4, rem = tid & 15;
#pragma unroll
            for (int it = 0; it < 8; it++) {
                const int ir = it >> 1, p = it & 1;
                const int rw = cp * 4 + p * 2, nc = ir * 32 + 2 * rem;
                *reinterpret_cast<uint32_t*>(&Bs[buf][rw * 136 + nc]) =
                    packh2(b_f[it * 4 + 0], b_f[it * 4 + 2]);
                *reinterpret_cast<uint32_t*>(&Bs[buf][(rw + 1) * 136 + nc]) =
                    packh2(b_f[it * 4 + 1], b_f[it * 4 + 3]);
            }
        } else {
#pragma unroll
            for (int it = 0; it < 4; it++) {
                const int row = (tid >> 4) + it * 8, col = (tid & 15) * 8;
                *reinterpret_cast<uint4*>(&Bs[buf][row * 136 + col]) = b_u[it];
            }
        }
    };

    float acc[4][8][4];
#pragma unroll
    for (int mt = 0; mt < 4; mt++)
#pragma unroll
        for (int nt = 0; nt < 8; nt++)
#pragma unroll
            for (int r = 0; r < 4; r++) acc[mt][nt][r] = 0.f;

    LDGA(0); LDGB(0); STSA(0); STSB(0);
    __syncthreads();

    constexpr int NIT = K / 32;
    for (int i = 0; i < NIT; i++) {
        const int buf = i & 1;
        if (i + 1 < NIT) { LDGA((i + 1) * 32); LDGB((i + 1) * 32); }

#pragma unroll
        for (int s = 0; s < 2; s++) {
            uint32_t a[4][4];
#pragma unroll
            for (int mt = 0; mt < 4; mt++)
                ldsm4(a[mt][0], a[mt][1], a[mt][2], a[mt][3],
                      aBase[buf] + ((m0w + mt * 16 + lb3 * 8 + lr) * 40 + s * 16 + lb4 * 8) * 2);
            uint32_t b[8][2];
#pragma unroll
            for (int np = 0; np < 4; np++)
                ldsm4t(b[2 * np][0], b[2 * np][1], b[2 * np + 1][0], b[2 * np + 1][1],
                       bBase[buf] + ((s * 16 + lb3 * 8 + lr) * 136 + n0w + np * 16 + lb4 * 8) * 2);
#pragma unroll
            for (int mt = 0; mt < 4; mt++)
#pragma unroll
                for (int nt = 0; nt < 8; nt++)
                    mma16(acc[mt][nt], a[mt], b[nt][0], b[nt][1]);
        }
        if (i + 1 < NIT) { STSA(buf ^ 1); STSB(buf ^ 1); }
        __syncthreads();
    }

#pragma unroll
    for (int mt = 0; mt < 4; mt++)
#pragma unroll
        for (int nt = 0; nt < 8; nt++) {
            const int row = row0 + m0w + mt * 16 + g;
            const int col = col0 + n0w + nt * 8 + 2 * t;
            if (OUTF32) {
                float* Cp = (float*)Cv + (size_t)z * M * N;
                float2 v0; v0.x = acc[mt][nt][0]; v0.y = acc[mt][nt][1];
                float2 v1; v1.x = acc[mt][nt][2]; v1.y = acc[mt][nt][3];
                *reinterpret_cast<float2*>(Cp + (size_t)row * N + col)       = v0;
                *reinterpret_cast<float2*>(Cp + (size_t)(row + 8) * N + col) = v1;
            } else {
                __half* Cp = (__half*)Cv + (size_t)z * M * N;
                *reinterpret_cast<uint32_t*>(Cp + (size_t)row * N + col) =
                    packh2(acc[mt][nt][0], acc[mt][nt][1]);
                *reinterpret_cast<uint32_t*>(Cp + (size_t)(row + 8) * N + col) =
                    packh2(acc[mt][nt][2], acc[mt][nt][3]);
            }
        }
}

// ---------------------------------------------------------------------------
// fp16 flash attention. 128 thr (4 warps), 128 queries/CTA, j-chunks of 128.
// Qs/Ks/Vs in native [d][pos] half layout (stride 136); fragments via
// ldmatrix(.trans). Register-resident P (S frag pairs are k-adjacent in fp16:
// no permutation). Scale 0.125 folded into wq upstream.
// ---------------------------------------------------------------------------
#define ATTN_SMEM (3 * 64 * 136 * 2)

__global__ __launch_bounds__(128, 2)
void attn_f16(const __half* __restrict__ Q, const __half* __restrict__ KV,
              __half* __restrict__ O)
{
    const int bb = blockIdx.z, h = blockIdx.y, i0 = blockIdx.x * 128;
    const int tid = threadIdx.x, lane = tid & 31, w = tid >> 5;
    const int g = lane >> 2, t = lane & 3;
    const int lr = lane & 7, lb3 = (lane >> 3) & 1, lb4 = (lane >> 4) & 1;

    const __half* Qb = Q  + ((size_t)bb * DIM + h * DHEAD) * HW;
    const __half* Kb = KV + ((size_t)bb * 2 * DIM + h * DHEAD) * LKV;
    const __half* Vb = KV + ((size_t)bb * 2 * DIM + DIM + h * DHEAD) * LKV;
    __half*       Ob = O  + ((size_t)bb * DIM + h * DHEAD) * HW;

    extern __shared__ __half smh[];
    __half* Qs = smh;
    __half* Ks = Qs + 64 * 136;
    __half* Vs = Ks + 64 * 136;
    const uint32_t qb = smem_u32(Qs), kb = smem_u32(Ks), vb = smem_u32(Vs);

    // Load Q tile [64 d][128 i] (half, native layout)
#pragma unroll
    for (int it = 0; it < 8; it++) {
        const int d = (tid >> 4) + it * 8, col = (tid & 15) * 8;
        *reinterpret_cast<uint4*>(&Qs[d * 136 + col]) =
            *reinterpret_cast<const uint4*>(Qb + (size_t)d * HW + i0 + col);
    }

    float o[2][8][4];
#pragma unroll
    for (int mt = 0; mt < 2; mt++)
#pragma unroll
        for (int nt = 0; nt < 8; nt++)
#pragma unroll
            for (int r = 0; r < 4; r++) o[mt][nt][r] = 0.f;
    float mrow[4], lrow[4];
#pragma unroll
    for (int r = 0; r < 4; r++) { mrow[r] = -1e30f; lrow[r] = 0.f; }

    for (int j0 = 0; j0 < LKV; j0 += 128) {
        __syncthreads();
#pragma unroll
        for (int it = 0; it < 8; it++) {
            const int d = (tid >> 4) + it * 8, col = (tid & 15) * 8;
            *reinterpret_cast<uint4*>(&Ks[d * 136 + col]) =
                *reinterpret_cast<const uint4*>(Kb + (size_t)d * LKV + j0 + col);
            *reinterpret_cast<uint4*>(&Vs[d * 136 + col]) =
                *reinterpret_cast<const uint4*>(Vb + (size_t)d * LKV + j0 + col);
        }
        __syncthreads();

        // Phase A: S = Q^T K  (warp tile 32 i x 128 j)
        float s[2][16][4];
#pragma unroll
        for (int mt = 0; mt < 2; mt++)
#pragma unroll
            for (int nt = 0; nt < 16; nt++)
#pragma unroll
                for (int r = 0; r < 4; r++) s[mt][nt][r] = 0.f;

#pragma unroll
        for (int ks = 0; ks < 4; ks++) {
            uint32_t a[2][4];
#pragma unroll
            for (int mt = 0; mt < 2; mt++)
                ldsm4t(a[mt][0], a[mt][1], a[mt][2], a[mt][3],
                       qb + ((16 * ks + lb4 * 8 + lr) * 136 + 32 * w + mt * 16 + lb3 * 8) * 2);
#pragma unroll
            for (int np = 0; np < 8; np++) {
                uint32_t b0, b1, b2, b3;
                ldsm4t(b0, b1, b2, b3,
                       kb + ((16 * ks + lb3 * 8 + lr) * 136 + np * 16 + lb4 * 8) * 2);
                mma16(s[0][2 * np],     a[0], b0, b1);
                mma16(s[0][2 * np + 1], a[0], b2, b3);
                mma16(s[1][2 * np],     a[1], b0, b1);
                mma16(s[1][2 * np + 1], a[1], b2, b3);
            }
        }

        // Online softmax (regs {0,1}=row g, {2,3}=row g+8)
        float fac[4];
#pragma unroll
        for (int mt = 0; mt < 2; mt++)
#pragma unroll
            for (int hh = 0; hh < 2; hh++) {
                const int idx = mt * 2 + hh;
                float mx = -1e30f;
#pragma unroll
                for (int nt = 0; nt < 16; nt++) {
                    mx = fmaxf(mx, s[mt][nt][2 * hh]);
                    mx = fmaxf(mx, s[mt][nt][2 * hh + 1]);
                }
                mx = fmaxf(mx, __shfl_xor_sync(0xffffffffu, mx, 1));
                mx = fmaxf(mx, __shfl_xor_sync(0xffffffffu, mx, 2));
                const float mn = fmaxf(mrow[idx], mx);
                fac[idx] = __expf(mrow[idx] - mn);
                mrow[idx] = mn;
                float ls = 0.f;
#pragma unroll
                for (int nt = 0; nt < 16; nt++) {
                    const float p0 = __expf(s[mt][nt][2 * hh]     - mn);
                    const float p1 = __expf(s[mt][nt][2 * hh + 1] - mn);
                    s[mt][nt][2 * hh] = p0; s[mt][nt][2 * hh + 1] = p1;
                    ls += p0 + p1;
                }
                lrow[idx] = lrow[idx] * fac[idx] + ls;
            }

#pragma unroll
        for (int mt = 0; mt < 2; mt++)
#pragma unroll
            for (int nt = 0; nt < 8; nt++) {
                o[mt][nt][0] *= fac[mt * 2];
                o[mt][nt][1] *= fac[mt * 2];
                o[mt][nt][2] *= fac[mt * 2 + 1];
                o[mt][nt][3] *= fac[mt * 2 + 1];
            }

        // Phase B: O += P @ V^T  (P packed from S regs; V native layout)
#pragma unroll
        for (int ks = 0; ks < 8; ks++) {
            uint32_t pa[2][4];
#pragma unroll
            for (int mt = 0; mt < 2; mt++) {
                pa[mt][0] = packh2(s[mt][2 * ks][0],     s[mt][2 * ks][1]);
                pa[mt][1] = packh2(s[mt][2 * ks][2],     s[mt][2 * ks][3]);
                pa[mt][2] = packh2(s[mt][2 * ks + 1][0], s[mt][2 * ks + 1][1]);
                pa[mt][3] = packh2(s[mt][2 * ks + 1][2], s[mt][2 * ks + 1][3]);
            }
#pragma unroll
            for (int np = 0; np < 4; np++) {
                uint32_t b0, b1, b2, b3;
                ldsm4(b0, b1, b2, b3,
                      vb + ((16 * np + lb4 * 8 + lr) * 136 + 16 * ks + lb3 * 8) * 2);
                mma16(o[0][2 * np],     pa[0], b0, b1);
                mma16(o[0][2 * np + 1], pa[0], b2, b3);
                mma16(o[1][2 * np],     pa[1], b0, b1);
                mma16(o[1][2 * np + 1], pa[1], b2, b3);
            }
        }
    }

    float inv[4];
#pragma unroll
    for (int idx = 0; idx < 4; idx++) {
        float ls = lrow[idx];
        ls += __shfl_xor_sync(0xffffffffu, ls, 1);
        ls += __shfl_xor_sync(0xffffffffu, ls, 2);
        inv[idx] = 1.f / ls;
    }

    // Stage O [d][i] half in smem (reuse Qs), then coalesced store
    __syncthreads();
    __half* Of = Qs;
#pragma unroll
    for (int mt = 0; mt < 2; mt++) {
        const int row = 32 * w + mt * 16 + g;
#pragma unroll
        for (int nt = 0; nt < 8; nt++) {
            const int d = nt * 8 + 2 * t;
            Of[d * 136 + row]           = __float2half(o[mt][nt][0] * inv[mt * 2]);
            Of[(d + 1) * 136 + row]     = __float2half(o[mt][nt][1] * inv[mt * 2]);
            Of[d * 136 + row + 8]       = __float2half(o[mt][nt][2] * inv[mt * 2 + 1]);
            Of[(d + 1) * 136 + row + 8] = __float2half(o[mt][nt][3] * inv[mt * 2 + 1]);
        }
    }
    __syncthreads();
#pragma unroll
    for (int it = 0; it < 8; it++) {
        const int d = (tid >> 4) + it * 8, col = (tid & 15) * 8;
        *reinterpret_cast<uint4*>(Ob + (size_t)d * HW + i0 + col) =
            *reinterpret_cast<const uint4*>(&Of[d * 136 + col]);
    }
}

// ---------------- launch ----------------
extern "C" void kernel_launch(void* const* d_in, const int* in_sizes, int n_in,
                              void* d_out, int out_size)
{
    const float* x    = (const float*)d_in[0];
    const float* wq   = (const float*)d_in[1];
    const float* wkv  = (const float*)d_in[2];
    const float* wout = (const float*)d_in[3];
    float* out = (float*)d_out;

    __half *qbuf, *kvbuf, *obuf;
    cudaGetSymbolAddress((void**)&qbuf,  g_q);
    cudaGetSymbolAddress((void**)&kvbuf, g_kv);
    cudaGetSymbolAddress((void**)&obuf,  g_o);

    cudaFuncSetAttribute(attn_f16,
                         cudaFuncAttributeMaxDynamicSharedMemorySize, ATTN_SMEM);

    // Q = (0.125*wq) @ X : half out
    gemm_f16<512, 4096, 512, 0, false, true>
        <<<dim3(32, 4, BATCH), 128>>>(wq, x, qbuf);
    // KV = wkv @ im2col(X) : half out
    gemm_f16<1024, 1024, 2048, 1, false, false>
        <<<dim3(8, 8, BATCH), 128>>>(wkv, x, kvbuf);
    // attention
    attn_f16<<<dim3(HW / 128, HEADS, BATCH), 128, ATTN_SMEM>>>(qbuf, kvbuf, obuf);
    // Y = wout @ O : fp32 out
    gemm_f16<512, 4096, 512, 2, true, false>
        <<<dim3(32, 4, BATCH), 128>>>(wout, obuf, out);
}

// round 10
// speedup vs baseline: 1.8634x; 1.0383x over previous
#include <cuda_runtime.h>
#include <cuda_fp16.h>
#include <cstdint>

#define BATCH 4
#define DIM   512
#define HEADS 8
#define DHEAD 64
#define HW    4096
#define LKV   1024

// fp16 scratch (device globals; allocation-free)
__device__ __half g_wq [512 * 512];
__device__ __half g_wkv[1024 * 2048];
__device__ __half g_wo [512 * 512];
__device__ __half g_xt [BATCH * HW * DIM];     // x^T    [b][pos][ch]
__device__ __half g_x2 [BATCH * LKV * 2048];   // im2col [b][n][k]
__device__ __half g_q  [BATCH * DIM * HW];     // Q      [b][ch][pos]
__device__ __half g_kv [BATCH * 2 * DIM * LKV];// KV     [b][och][ij]
__device__ __half g_ot [BATCH * HW * DIM];     // attnO^T[b][pos][ch]

// ---------------- helpers ----------------
__device__ __forceinline__ uint32_t packh2(float lo, float hi) {
    uint32_t r;
    asm("cvt.rn.f16x2.f32 %0, %1, %2;" : "=r"(r) : "f"(hi), "f"(lo));
    return r;
}
__device__ __forceinline__ uint32_t smem_u32(const void* p) {
    uint32_t a;
    asm("{ .reg .u64 t; cvta.to.shared.u64 t, %1; cvt.u32.u64 %0, t; }" : "=r"(a) : "l"(p));
    return a;
}
__device__ __forceinline__ void ldsm4(uint32_t& r0, uint32_t& r1, uint32_t& r2, uint32_t& r3,
                                      uint32_t addr) {
    asm volatile("ldmatrix.sync.aligned.m8n8.x4.shared.b16 {%0,%1,%2,%3}, [%4];"
                 : "=r"(r0), "=r"(r1), "=r"(r2), "=r"(r3) : "r"(addr));
}
__device__ __forceinline__ void ldsm4t(uint32_t& r0, uint32_t& r1, uint32_t& r2, uint32_t& r3,
                                       uint32_t addr) {
    asm volatile("ldmatrix.sync.aligned.m8n8.x4.trans.shared.b16 {%0,%1,%2,%3}, [%4];"
                 : "=r"(r0), "=r"(r1), "=r"(r2), "=r"(r3) : "r"(addr));
}
__device__ __forceinline__ void mma16(float* d, const uint32_t* a, uint32_t b0, uint32_t b1) {
    asm volatile("mma.sync.aligned.m16n8k16.row.col.f32.f16.f16.f32 "
        "{%0,%1,%2,%3},{%4,%5,%6,%7},{%8,%9},{%0,%1,%2,%3};"
        : "+f"(d[0]), "+f"(d[1]), "+f"(d[2]), "+f"(d[3])
        : "r"(a[0]), "r"(a[1]), "r"(a[2]), "r"(a[3]), "r"(b0), "r"(b1));
}
__device__ __forceinline__ void cpa16(uint32_t dst, const void* src) {
    asm volatile("cp.async.cg.shared.global [%0], [%1], 16;" :: "r"(dst), "l"(src));
}
#define CP_COMMIT() asm volatile("cp.async.commit_group;" ::: "memory")
template <int NN> __device__ __forceinline__ void cp_wait() {
    asm volatile("cp.async.wait_group %0;" :: "n"(NN) : "memory");
}

// ---------------- prepass: fp32 -> fp16 conversions ----------------
__global__ __launch_bounds__(256)
void cvt_kernel(const float* __restrict__ s, __half* __restrict__ d, int n4, float scale)
{
    const int i = blockIdx.x * 256 + threadIdx.x;
    if (i < n4) {
        float4 v = reinterpret_cast<const float4*>(s)[i];
        reinterpret_cast<uint2*>(d)[i] =
            make_uint2(packh2(v.x * scale, v.y * scale), packh2(v.z * scale, v.w * scale));
    }
}

// x [b][512][4096] f32 -> x^T [b][4096][512] half
__global__ void trcvt_kernel(const float* __restrict__ S, __half* __restrict__ D)
{
    __shared__ float t[32][33];
    const float* s = S + (size_t)blockIdx.z * DIM * HW;
    __half*      d = D + (size_t)blockIdx.z * HW * DIM;
    const int c0 = blockIdx.x * 32, r0 = blockIdx.y * 32;
    const int tx = threadIdx.x, ty = threadIdx.y;
#pragma unroll
    for (int j = 0; j < 32; j += 8)
        t[ty + j][tx] = s[(size_t)(r0 + ty + j) * HW + c0 + tx];
    __syncthreads();
#pragma unroll
    for (int j = 0; j < 32; j += 8)
        d[(size_t)(c0 + ty + j) * DIM + r0 + tx] = __float2half(t[tx][ty + j]);
}

// im2col: x2[b][n][c*4 + p*2 + q] = x[b][c][(2i+p)*64 + 2j+q], n = 32i+j (half out)
__global__ __launch_bounds__(256)
void im2col_kernel(const float* __restrict__ X, __half* __restrict__ T)
{
    const int id = blockIdx.x * 256 + threadIdx.x;
    const int c = id & 511;
    const int n = (id >> 9) & 1023;
    const int b = id >> 19;
    const int i = n >> 5, j = n & 31;
    const float* xp = X + ((size_t)b * DIM + c) * HW + i * 128 + j * 2;
    float2 v0 = *reinterpret_cast<const float2*>(xp);
    float2 v1 = *reinterpret_cast<const float2*>(xp + 64);
    *reinterpret_cast<uint2*>(T + ((size_t)b * LKV + n) * 2048 + c * 4) =
        make_uint2(packh2(v0.x, v0.y), packh2(v1.x, v1.y));
}

// ---------------------------------------------------------------------------
// Unified all-half GEMM: C[b][m][n] = sum_k A[m][k] * B[b][n][k]
// 128 thr, 4 warps, warp tile 64x64, BK=32, cp.async double-buffered.
// As/Bs both [row][32k + 8 pad] half (stride 40) — conflict-free ldsm rows.
// ---------------------------------------------------------------------------
template <int M, int N, int K, bool OUTF32>
__global__ __launch_bounds__(128, 3)
void gemm_h(const __half* __restrict__ A, const __half* __restrict__ B, void* Cv)
{
    __shared__ __half As[2][128 * 40];
    __shared__ __half Bs[2][128 * 40];

    const int tid = threadIdx.x, lane = tid & 31, w = tid >> 5;
    const int g = lane >> 2, t = lane & 3;
    const int lr = lane & 7, lb3 = (lane >> 3) & 1, lb4 = (lane >> 4) & 1;
    const int m0w = (w >> 1) * 64, n0w = (w & 1) * 64;
    const int row0 = blockIdx.y * 128, col0 = blockIdx.x * 128;
    const int z = blockIdx.z;

    const __half* Bp = B + (size_t)z * N * K;
    uint32_t aBase[2] = { smem_u32(&As[0][0]), smem_u32(&As[1][0]) };
    uint32_t bBase[2] = { smem_u32(&Bs[0][0]), smem_u32(&Bs[1][0]) };

    auto LOAD = [&](int k0, int buf) {
        const __half* ar = A  + (size_t)(row0 + tid) * K + k0;
        const __half* br = Bp + (size_t)(col0 + tid) * K + k0;
        const uint32_t ad = aBase[buf] + tid * 80;
        const uint32_t bd = bBase[buf] + tid * 80;
#pragma unroll
        for (int u = 0; u < 4; u++) {
            cpa16(ad + u * 16, ar + u * 8);
            cpa16(bd + u * 16, br + u * 8);
        }
    };

    float acc[4][8][4];
#pragma unroll
    for (int mt = 0; mt < 4; mt++)
#pragma unroll
        for (int nt = 0; nt < 8; nt++)
#pragma unroll
            for (int r = 0; r < 4; r++) acc[mt][nt][r] = 0.f;

    LOAD(0, 0);
    CP_COMMIT();

    constexpr int NIT = K / 32;
    for (int i = 0; i < NIT; i++) {
        const int buf = i & 1;
        if (i + 1 < NIT) {
            LOAD((i + 1) * 32, buf ^ 1);
            CP_COMMIT();
            cp_wait<1>();
        } else {
            cp_wait<0>();
        }
        __syncthreads();

#pragma unroll
        for (int s = 0; s < 2; s++) {
            uint32_t a[4][4];
#pragma unroll
            for (int mt = 0; mt < 4; mt++)
                ldsm4(a[mt][0], a[mt][1], a[mt][2], a[mt][3],
                      aBase[buf] + ((m0w + mt * 16 + lb3 * 8 + lr) * 40 + s * 16 + lb4 * 8) * 2);
            uint32_t b[8][2];
#pragma unroll
            for (int np = 0; np < 4; np++) {
                uint32_t r0, r1, r2, r3;
                ldsm4(r0, r1, r2, r3,
                      bBase[buf] + ((n0w + np * 16 + lb3 * 8 + lr) * 40 + s * 16 + lb4 * 8) * 2);
                b[2 * np][0] = r0; b[2 * np][1] = r2;       // n 0-7 : k0-7, k8-15
                b[2 * np + 1][0] = r1; b[2 * np + 1][1] = r3; // n 8-15
            }
#pragma unroll
            for (int mt = 0; mt < 4; mt++)
#pragma unroll
                for (int nt = 0; nt < 8; nt++)
                    mma16(acc[mt][nt], a[mt], b[nt][0], b[nt][1]);
        }
        __syncthreads();
    }

#pragma unroll
    for (int mt = 0; mt < 4; mt++)
#pragma unroll
        for (int nt = 0; nt < 8; nt++) {
            const int row = row0 + m0w + mt * 16 + g;
            const int col = col0 + n0w + nt * 8 + 2 * t;
            if (OUTF32) {
                float* Cp = (float*)Cv + (size_t)z * M * N;
                float2 v0; v0.x = acc[mt][nt][0]; v0.y = acc[mt][nt][1];
                float2 v1; v1.x = acc[mt][nt][2]; v1.y = acc[mt][nt][3];
                *reinterpret_cast<float2*>(Cp + (size_t)row * N + col)       = v0;
                *reinterpret_cast<float2*>(Cp + (size_t)(row + 8) * N + col) = v1;
            } else {
                __half* Cp = (__half*)Cv + (size_t)z * M * N;
                *reinterpret_cast<uint32_t*>(Cp + (size_t)row * N + col) =
                    packh2(acc[mt][nt][0], acc[mt][nt][1]);
                *reinterpret_cast<uint32_t*>(Cp + (size_t)(row + 8) * N + col) =
                    packh2(acc[mt][nt][2], acc[mt][nt][3]);
            }
        }
}

// ---------------------------------------------------------------------------
// fp16 flash attention, cp.async double-buffered K/V chunks.
// 128 thr (4 warps), 128 queries/CTA, j-chunks of 128. Register-resident P.
// Output written as O^T [pos][ch] for the out-GEMM.
// Smem: Qs [64][136] + 2 x (Ks+Vs) [64][136] = 87,040 B -> 2 CTAs/SM.
// ---------------------------------------------------------------------------
#define ATTN_SMEM ((64 * 136 + 4 * 64 * 136) * 2)

__global__ __launch_bounds__(128, 2)
void attn_f16(const __half* __restrict__ Q, const __half* __restrict__ KV,
              __half* __restrict__ OT)
{
    const int bb = blockIdx.z, h = blockIdx.y, i0 = blockIdx.x * 128;
    const int tid = threadIdx.x, lane = tid & 31, w = tid >> 5;
    const int g = lane >> 2, t = lane & 3;
    const int lr = lane & 7, lb3 = (lane >> 3) & 1, lb4 = (lane >> 4) & 1;

    const __half* Qb = Q  + ((size_t)bb * DIM + h * DHEAD) * HW;
    const __half* Kb = KV + ((size_t)bb * 2 * DIM + h * DHEAD) * LKV;
    const __half* Vb = KV + ((size_t)bb * 2 * DIM + DIM + h * DHEAD) * LKV;

    extern __shared__ __half smh[];
    __half* Qs  = smh;
    __half* KV0 = Qs + 64 * 136;   // buffer 0: K then V
    const uint32_t qb   = smem_u32(Qs);
    const uint32_t kvb0 = smem_u32(KV0);

    // Load Q tile [64 d][128 i]
#pragma unroll
    for (int it = 0; it < 8; it++) {
        const int d = (tid >> 4) + it * 8, col = (tid & 15) * 8;
        *reinterpret_cast<uint4*>(&Qs[d * 136 + col]) =
            *reinterpret_cast<const uint4*>(Qb + (size_t)d * HW + i0 + col);
    }

    auto LOADKV = [&](int j0, int buf) {
        const uint32_t base = kvb0 + buf * (2 * 64 * 136 * 2);
#pragma unroll
        for (int it = 0; it < 16; it++) {
            const int idx = tid + it * 128;          // 0..2047
            const int sel = idx >> 10;               // 0:K 1:V
            const int r = (idx >> 4) & 63;
            const int c = idx & 15;
            const __half* src = (sel ? Vb : Kb) + (size_t)r * LKV + j0 + c * 8;
            cpa16(base + (sel * 64 * 136 + r * 136 + c * 8) * 2, src);
        }
    };

    float o[2][8][4];
#pragma unroll
    for (int mt = 0; mt < 2; mt++)
#pragma unroll
        for (int nt = 0; nt < 8; nt++)
#pragma unroll
            for (int r = 0; r < 4; r++) o[mt][nt][r] = 0.f;
    float mrow[4], lrow[4];
#pragma unroll
    for (int r = 0; r < 4; r++) { mrow[r] = -1e30f; lrow[r] = 0.f; }

    LOADKV(0, 0);
    CP_COMMIT();

    for (int jc = 0; jc < 8; jc++) {
        const int buf = jc & 1;
        if (jc + 1 < 8) {
            LOADKV((jc + 1) * 128, buf ^ 1);
            CP_COMMIT();
            cp_wait<1>();
        } else {
            cp_wait<0>();
        }
        __syncthreads();

        const uint32_t kb = kvb0 + buf * (2 * 64 * 136 * 2);
        const uint32_t vb = kb + 64 * 136 * 2;

        // Phase A: S = Q^T K (warp tile 32 i x 128 j)
        float s[2][16][4];
#pragma unroll
        for (int mt = 0; mt < 2; mt++)
#pragma unroll
            for (int nt = 0; nt < 16; nt++)
#pragma unroll
                for (int r = 0; r < 4; r++) s[mt][nt][r] = 0.f;

#pragma unroll
        for (int ks = 0; ks < 4; ks++) {
            uint32_t a[2][4];
#pragma unroll
            for (int mt = 0; mt < 2; mt++)
                ldsm4t(a[mt][0], a[mt][1], a[mt][2], a[mt][3],
                       qb + ((16 * ks + lb4 * 8 + lr) * 136 + 32 * w + mt * 16 + lb3 * 8) * 2);
#pragma unroll
            for (int np = 0; np < 8; np++) {
                uint32_t b0, b1, b2, b3;
                ldsm4t(b0, b1, b2, b3,
                       kb + ((16 * ks + lb3 * 8 + lr) * 136 + np * 16 + lb4 * 8) * 2);
                mma16(s[0][2 * np],     a[0], b0, b1);
                mma16(s[0][2 * np + 1], a[0], b2, b3);
                mma16(s[1][2 * np],     a[1], b0, b1);
                mma16(s[1][2 * np + 1], a[1], b2, b3);
            }
        }

        // Online softmax
        float fac[4];
#pragma unroll
        for (int mt = 0; mt < 2; mt++)
#pragma unroll
            for (int hh = 0; hh < 2; hh++) {
                const int idx = mt * 2 + hh;
                float mx = -1e30f;
#pragma unroll
                for (int nt = 0; nt < 16; nt++) {
                    mx = fmaxf(mx, s[mt][nt][2 * hh]);
                    mx = fmaxf(mx, s[mt][nt][2 * hh + 1]);
                }
                mx = fmaxf(mx, __shfl_xor_sync(0xffffffffu, mx, 1));
                mx = fmaxf(mx, __shfl_xor_sync(0xffffffffu, mx, 2));
                const float mn = fmaxf(mrow[idx], mx);
                fac[idx] = __expf(mrow[idx] - mn);
                mrow[idx] = mn;
                float ls = 0.f;
#pragma unroll
                for (int nt = 0; nt < 16; nt++) {
                    const float p0 = __expf(s[mt][nt][2 * hh]     - mn);
                    const float p1 = __expf(s[mt][nt][2 * hh + 1] - mn);
                    s[mt][nt][2 * hh] = p0; s[mt][nt][2 * hh + 1] = p1;
                    ls += p0 + p1;
                }
                lrow[idx] = lrow[idx] * fac[idx] + ls;
            }

#pragma unroll
        for (int mt = 0; mt < 2; mt++)
#pragma unroll
            for (int nt = 0; nt < 8; nt++) {
                o[mt][nt][0] *= fac[mt * 2];
                o[mt][nt][1] *= fac[mt * 2];
                o[mt][nt][2] *= fac[mt * 2 + 1];
                o[mt][nt][3] *= fac[mt * 2 + 1];
            }

        // Phase B: O += P @ V^T
#pragma unroll
        for (int ks = 0; ks < 8; ks++) {
            uint32_t pa[2][4];
#pragma unroll
            for (int mt = 0; mt < 2; mt++) {
                pa[mt][0] = packh2(s[mt][2 * ks][0],     s[mt][2 * ks][1]);
                pa[mt][1] = packh2(s[mt][2 * ks][2],     s[mt][2 * ks][3]);
                pa[mt][2] = packh2(s[mt][2 * ks + 1][0], s[mt][2 * ks + 1][1]);
                pa[mt][3] = packh2(s[mt][2 * ks + 1][2], s[mt][2 * ks + 1][3]);
            }
#pragma unroll
            for (int np = 0; np < 4; np++) {
                uint32_t b0, b1, b2, b3;
                ldsm4(b0, b1, b2, b3,
                      vb + ((16 * np + lb4 * 8 + lr) * 136 + 16 * ks + lb3 * 8) * 2);
                mma16(o[0][2 * np],     pa[0], b0, b1);
                mma16(o[0][2 * np + 1], pa[0], b2, b3);
                mma16(o[1][2 * np],     pa[1], b0, b1);
                mma16(o[1][2 * np + 1], pa[1], b2, b3);
            }
        }
        __syncthreads();
    }

    float inv[4];
#pragma unroll
    for (int idx = 0; idx < 4; idx++) {
        float ls = lrow[idx];
        ls += __shfl_xor_sync(0xffffffffu, ls, 1);
        ls += __shfl_xor_sync(0xffffffffu, ls, 2);
        inv[idx] = 1.f / ls;
    }

    // Stage O as [row][d] (stride 72) in the KV buffer area, then write O^T
    __syncthreads();
    __half* Of = KV0;
#pragma unroll
    for (int mt = 0; mt < 2; mt++) {
        const int row = 32 * w + mt * 16 + g;
#pragma unroll
        for (int nt = 0; nt < 8; nt++) {
            const int d = nt * 8 + 2 * t;
            Of[row * 72 + d]           = __float2half(o[mt][nt][0] * inv[mt * 2]);
            Of[row * 72 + d + 1]       = __float2half(o[mt][nt][1] * inv[mt * 2]);
            Of[(row + 8) * 72 + d]     = __float2half(o[mt][nt][2] * inv[mt * 2 + 1]);
            Of[(row + 8) * 72 + d + 1] = __float2half(o[mt][nt][3] * inv[mt * 2 + 1]);
        }
    }
    __syncthreads();

    __half* dst = OT + ((size_t)bb * HW + i0 + tid) * DIM + h * DHEAD;
#pragma unroll
    for (int u = 0; u < 8; u++)
        reinterpret_cast<uint4*>(dst)[u] =
            *reinterpret_cast<const uint4*>(Of + tid * 72 + u * 8);
}

// ---------------- launch ----------------
extern "C" void kernel_launch(void* const* d_in, const int* in_sizes, int n_in,
                              void* d_out, int out_size)
{
    const float* x    = (const float*)d_in[0];
    const float* wq   = (const float*)d_in[1];
    const float* wkv  = (const float*)d_in[2];
    const float* wout = (const float*)d_in[3];
    float* out = (float*)d_out;

    __half *wqh, *wkvh, *woh, *xt, *x2, *qh, *kvh, *ot;
    cudaGetSymbolAddress((void**)&wqh,  g_wq);
    cudaGetSymbolAddress((void**)&wkvh, g_wkv);
    cudaGetSymbolAddress((void**)&woh,  g_wo);
    cudaGetSymbolAddress((void**)&xt,   g_xt);
    cudaGetSymbolAddress((void**)&x2,   g_x2);
    cudaGetSymbolAddress((void**)&qh,   g_q);
    cudaGetSymbolAddress((void**)&kvh,  g_kv);
    cudaGetSymbolAddress((void**)&ot,   g_ot);

    cudaFuncSetAttribute(attn_f16,
                         cudaFuncAttributeMaxDynamicSharedMemorySize, ATTN_SMEM);

    // prepass: weights + activations to fp16 (0.125 folded into wq)
    cvt_kernel<<<(512 * 512 / 4 + 255) / 256, 256>>>(wq, wqh, 512 * 512 / 4, 0.125f);
    cvt_kernel<<<(1024 * 2048 / 4 + 255) / 256, 256>>>(wkv, wkvh, 1024 * 2048 / 4, 1.f);
    cvt_kernel<<<(512 * 512 / 4 + 255) / 256, 256>>>(wout, woh, 512 * 512 / 4, 1.f);
    trcvt_kernel<<<dim3(128, 16, BATCH), dim3(32, 8)>>>(x, xt);
    im2col_kernel<<<BATCH * LKV * 512 / 256, 256>>>(x, x2);

    // Q = (0.125 wq) @ x : [ch][pos] half
    gemm_h<512, 4096, 512, false><<<dim3(32, 4, BATCH), 128>>>(wqh, xt, qh);
    // KV = wkv @ im2col(x) : [och][ij] half
    gemm_h<1024, 1024, 2048, false><<<dim3(8, 8, BATCH), 128>>>(wkvh, x2, kvh);
    // attention -> O^T [pos][ch] half
    attn_f16<<<dim3(HW / 128, HEADS, BATCH), 128, ATTN_SMEM>>>(qh, kvh, ot);
    // Y = wout @ O : fp32 out
    gemm_h<512, 4096, 512, true><<<dim3(32, 4, BATCH), 128>>>(woh, ot, out);
}